// round 14
// baseline (speedup 1.0000x reference)
#include <cuda_runtime.h>
#include <cstdint>

// Problem constants
#define BATCH   4
#define SEQ     4096
#define DMODEL  2048
#define TOKENS  (BATCH * SEQ)     // 16384
#define NCPAD   36                // 16 q + 16 k + w + pad (float4-aligned pitch)
#define DSPLIT  8
#define DCHUNK  (DMODEL / DSPLIT) // 256

typedef unsigned long long u64;

// Scratch (static device globals: no dynamic allocation allowed)
__device__ float g_part[(size_t)DSPLIT * TOKENS * NCPAD];   // ~18.9 MB
__device__ float g_q[TOKENS * 16];
__device__ float g_k[TOKENS * 16];
__device__ float g_w[TOKENS];

// ---- packed f32x2 helpers (FFMA2 path, PTX-only on sm_103a) ----
__device__ __forceinline__ u64 pack2(float lo, float hi) {
    u64 r; asm("mov.b64 %0, {%1, %2};" : "=l"(r) : "f"(lo), "f"(hi)); return r;
}
__device__ __forceinline__ void unpack2(u64 v, float& lo, float& hi) {
    asm("mov.b64 {%0, %1}, %2;" : "=f"(lo), "=f"(hi) : "l"(v));
}
__device__ __forceinline__ u64 fma2(u64 a, u64 b, u64 c) {
    u64 d; asm("fma.rn.f32x2 %0, %1, %2, %3;" : "=l"(d) : "l"(a), "l"(b), "l"(c)); return d;
}

// ============================================================================
// Kernel 1: projection partials. Grid (DSPLIT, 64) = 512 blocks, 128 threads.
// CROSSBAR-AWARE micro-tile: thread = (tg, cg), cg = tid&1 splits the 36
// (padded) output cols into two 9-col-pair halves; tg = tid>>1 owns 4 tokens.
// Per warp-k crossbar traffic: W 4xLDS.128 + 1xLDS.64 (2 distinct 16B regions
// per instr -> 1 wavefront each) + x 4xLDS.32 (swizzled, conflict-free)
// = ~9 crossbar-cyc  vs  36 FFMA2 = 72 fma-pipe-cyc  -> crossbar finally
// unbound (4 SMSP x 9 = 36 < 72), fma pipe can approach saturation.
// x staged via R9's proven coalesced LDG.128 + conflict-free scalar STS,
// plus a ^16 column swizzle so the 4-token reads are also conflict-free.
// ============================================================================
#define XSW(row, col) xs[row][(col) ^ ((((row) >> 5) & 1) << 4)]

__global__ __launch_bounds__(128)
void proj_kernel(const float* __restrict__ x,
                 const float* __restrict__ Wq,
                 const float* __restrict__ Wk,
                 const float* __restrict__ Ww)
{
    __shared__ float xs[256][33];   // 33.8 KB
    __shared__ float ws[32][36];    //  4.6 KB

    const int tid   = threadIdx.x;
    const int cg    = tid & 1;       // column half: 0 -> cols 0-15+{32,33}
    const int tg    = tid >> 1;      //              1 -> cols 16-31+{34,35}
    const int dbase = blockIdx.x * DCHUNK;
    const int tok0  = blockIdx.y * 256;

    u64 acc[4][9];                   // [token][col-pair] = 36 u64
    #pragma unroll
    for (int m = 0; m < 4; m++)
        #pragma unroll
        for (int p = 0; p < 9; p++) acc[m][p] = 0ull;

    const int wrow = tid >> 2;       // W staging: 32 rows x 4 quads
    const int wq   = (tid & 3) * 4;

    #pragma unroll 1
    for (int dt = 0; dt < DCHUNK; dt += 32) {
        const int d0 = dbase + dt;
        __syncthreads();   // previous tile fully consumed

        // ---- stage x tile: 256 tokens x 32 d, coalesced LDG.128,
        //      conflict-free swizzled scalar STS ----
        #pragma unroll
        for (int i = 0; i < 16; i++) {
            int task = tid + 128 * i;
            int row  = task >> 3;
            int c4   = (task & 7) * 4;
            const float4 v = *reinterpret_cast<const float4*>(
                &x[(size_t)(tok0 + row) * DMODEL + d0 + c4]);
            XSW(row, c4 + 0) = v.x;
            XSW(row, c4 + 1) = v.y;
            XSW(row, c4 + 2) = v.z;
            XSW(row, c4 + 3) = v.w;
        }

        // ---- stage W tile: 32 x 36 ----
        {
            const float4 vq = *reinterpret_cast<const float4*>(
                &Wq[(size_t)(d0 + wrow) * 16 + wq]);
            *reinterpret_cast<float4*>(&ws[wrow][wq]) = vq;
            const float4 vk = *reinterpret_cast<const float4*>(
                &Wk[(size_t)(d0 + wrow) * 16 + wq]);
            *reinterpret_cast<float4*>(&ws[wrow][16 + wq]) = vk;
            if (tid < 32) {
                ws[tid][32] = Ww[d0 + tid];
                ws[tid][33] = 0.f; ws[tid][34] = 0.f; ws[tid][35] = 0.f;
            }
        }
        __syncthreads();

        // ---- compute: 32 k-steps ----
        #pragma unroll 8
        for (int k = 0; k < 32; k++) {
            // W fragment for this col half: 8 pairs + 1 tail pair
            const float* wp = &ws[k][cg * 16];
            const ulonglong2 w01 = *reinterpret_cast<const ulonglong2*>(wp);
            const ulonglong2 w23 = *reinterpret_cast<const ulonglong2*>(wp + 4);
            const ulonglong2 w45 = *reinterpret_cast<const ulonglong2*>(wp + 8);
            const ulonglong2 w67 = *reinterpret_cast<const ulonglong2*>(wp + 12);
            const u64 w8 = *reinterpret_cast<const u64*>(&ws[k][32 + cg * 2]);

            #pragma unroll
            for (int m = 0; m < 4; m++) {
                const int row = 4 * tg + m;
                const float v = XSW(row, k);
                const u64 xv = pack2(v, v);
                acc[m][0] = fma2(xv, w01.x, acc[m][0]);
                acc[m][1] = fma2(xv, w01.y, acc[m][1]);
                acc[m][2] = fma2(xv, w23.x, acc[m][2]);
                acc[m][3] = fma2(xv, w23.y, acc[m][3]);
                acc[m][4] = fma2(xv, w45.x, acc[m][4]);
                acc[m][5] = fma2(xv, w45.y, acc[m][5]);
                acc[m][6] = fma2(xv, w67.x, acc[m][6]);
                acc[m][7] = fma2(xv, w67.y, acc[m][7]);
                acc[m][8] = fma2(xv, w8,    acc[m][8]);
            }
        }
    }

    // ---- write partials: cg0 -> cols 0-15 + {32,33}; cg1 -> cols 16-31 ----
    #pragma unroll
    for (int m = 0; m < 4; m++) {
        const int tok = tok0 + 4 * tg + m;
        float* p = &g_part[((size_t)blockIdx.x * TOKENS + tok) * NCPAD];
        #pragma unroll
        for (int q = 0; q < 4; q++) {
            ulonglong2 v; v.x = acc[m][2 * q]; v.y = acc[m][2 * q + 1];
            *reinterpret_cast<ulonglong2*>(&p[cg * 16 + 4 * q]) = v;
        }
        *reinterpret_cast<u64*>(&p[32 + cg * 2]) = acc[m][8];
    }
}

// ============================================================================
// Kernel 2: reduce D-split partials (float4-vectorized, 9 quads/token).
// ============================================================================
__global__ __launch_bounds__(256)
void reduce_kernel()
{
    int i = blockIdx.x * 256 + threadIdx.x;   // 0 .. 16384*9-1
    int tok = i / 9, c4 = i - tok * 9;
    float4 s = make_float4(0.f, 0.f, 0.f, 0.f);
    #pragma unroll
    for (int r = 0; r < DSPLIT; r++) {
        const float4 v = *reinterpret_cast<const float4*>(
            &g_part[((size_t)r * TOKENS + tok) * NCPAD + 4 * c4]);
        s.x += v.x; s.y += v.y; s.z += v.z; s.w += v.w;
    }
    if (c4 < 4)
        *reinterpret_cast<float4*>(&g_q[tok * 16 + 4 * c4]) = s;
    else if (c4 < 8)
        *reinterpret_cast<float4*>(&g_k[tok * 16 + 4 * (c4 - 4)]) = s;
    else
        g_w[tok] = s.x;
}

// ============================================================================
// Kernel 3: out[b,t,s] = relu(Q[b,t] . K[b,s]) * w[b,t]   (R9, unchanged)
// Grid (32 s-tiles, 32 t-tiles, 4) = 4096 blocks, 256 threads.
// Tile 128t x 128s, micro-tile 8t x 8s (s-pairs in f32x2).
// ============================================================================
__device__ __forceinline__ int kt_col(int s) {
    int st = s >> 3;
    return 8 * st + 4 * (st >> 2) + (s & 7);
}

__global__ __launch_bounds__(256)
void dot_kernel(float* __restrict__ out)
{
    __shared__ u64   qs2[128][17];   // [t][d] value-duplicated pairs (17.4 KB)
    __shared__ float kt[16][148];    // [d][s] transposed, swizzled (9.5 KB)
    __shared__ float wts[128];

    const int tid = threadIdx.x;
    const int tt  = tid >> 4;        // 0..15 : t-thread
    const int st  = tid & 15;        // 0..15 : s-thread (8 s each)

    const int b     = blockIdx.z;
    const int tbase = blockIdx.y * 128;
    const int sbase = blockIdx.x * 128;
    const int tokq  = b * SEQ + tbase;
    const int tokk  = b * SEQ + sbase;

    // Stage Q tile duplicated: 128 rows x 16 -> u64 dup pairs
    #pragma unroll
    for (int i = 0; i < 2; i++) {
        int task = tid + 256 * i;
        int row = task >> 2, q = (task & 3) * 4;
        const float4 v = *reinterpret_cast<const float4*>(
            &g_q[(size_t)(tokq + row) * 16 + q]);
        qs2[row][q + 0] = pack2(v.x, v.x);
        qs2[row][q + 1] = pack2(v.y, v.y);
        qs2[row][q + 2] = pack2(v.z, v.z);
        qs2[row][q + 3] = pack2(v.w, v.w);
    }
    // Stage K transposed + swizzled: kt[d][col(s)] = K[s][d]
    #pragma unroll
    for (int i = 0; i < 2; i++) {
        int task = tid + 256 * i;
        int s = task >> 2, q = (task & 3) * 4;
        const float4 v = *reinterpret_cast<const float4*>(
            &g_k[(size_t)(tokk + s) * 16 + q]);
        const int c = kt_col(s);
        kt[q + 0][c] = v.x;
        kt[q + 1][c] = v.y;
        kt[q + 2][c] = v.z;
        kt[q + 3][c] = v.w;
    }
    if (tid < 128) wts[tid] = g_w[tokq + tid];
    __syncthreads();

    const int c0 = 8 * st + 4 * (st >> 2);   // this thread's kt column base

    u64 acc[8][4];
    #pragma unroll
    for (int i = 0; i < 8; i++)
        #pragma unroll
        for (int j = 0; j < 4; j++) acc[i][j] = 0ull;

    #pragma unroll
    for (int d = 0; d < 16; d++) {
        const ulonglong2 ka = *reinterpret_cast<const ulonglong2*>(&kt[d][c0]);
        const ulonglong2 kb = *reinterpret_cast<const ulonglong2*>(&kt[d][c0 + 4]);
        #pragma unroll
        for (int i = 0; i < 8; i++) {
            const u64 q2 = qs2[tt + 16 * i][d];
            acc[i][0] = fma2(q2, ka.x, acc[i][0]);
            acc[i][1] = fma2(q2, ka.y, acc[i][1]);
            acc[i][2] = fma2(q2, kb.x, acc[i][2]);
            acc[i][3] = fma2(q2, kb.y, acc[i][3]);
        }
    }

    // Epilogue: relu, * w[t], 2x STG.128 per row
    #pragma unroll
    for (int i = 0; i < 8; i++) {
        const int t = tbase + tt + 16 * i;
        const float wt = wts[tt + 16 * i];
        float lo, hi;
        float4 oa, ob;
        unpack2(acc[i][0], lo, hi);
        oa.x = fmaxf(lo, 0.f) * wt;  oa.y = fmaxf(hi, 0.f) * wt;
        unpack2(acc[i][1], lo, hi);
        oa.z = fmaxf(lo, 0.f) * wt;  oa.w = fmaxf(hi, 0.f) * wt;
        unpack2(acc[i][2], lo, hi);
        ob.x = fmaxf(lo, 0.f) * wt;  ob.y = fmaxf(hi, 0.f) * wt;
        unpack2(acc[i][3], lo, hi);
        ob.z = fmaxf(lo, 0.f) * wt;  ob.w = fmaxf(hi, 0.f) * wt;
        float* o = &out[((size_t)(b * SEQ + t)) * SEQ + sbase + st * 8];
        *reinterpret_cast<float4*>(o)     = oa;
        *reinterpret_cast<float4*>(o + 4) = ob;
    }
}

// ============================================================================
extern "C" void kernel_launch(void* const* d_in, const int* in_sizes, int n_in,
                              void* d_out, int out_size)
{
    const float* x  = (const float*)d_in[0];
    const float* Wq = (const float*)d_in[1];
    const float* Wk = (const float*)d_in[2];
    const float* Ww = (const float*)d_in[3];
    float* out = (float*)d_out;

    proj_kernel<<<dim3(DSPLIT, TOKENS / 256), 128>>>(x, Wq, Wk, Ww);
    reduce_kernel<<<(TOKENS * 9) / 256, 256>>>();
    dot_kernel<<<dim3(SEQ / 128, SEQ / 128, BATCH), 256>>>(out);
}

// round 15
// speedup vs baseline: 1.4640x; 1.4640x over previous
#include <cuda_runtime.h>
#include <cstdint>

// Problem constants
#define BATCH   4
#define SEQ     4096
#define DMODEL  2048
#define TOKENS  (BATCH * SEQ)     // 16384
#define NCPAD   36                // 16 q + 16 k + w + pad (float4-aligned pitch)
#define DSPLIT  8
#define DCHUNK  (DMODEL / DSPLIT) // 256

typedef unsigned long long u64;

// Scratch (static device globals: no dynamic allocation allowed)
__device__ float g_part[(size_t)DSPLIT * TOKENS * NCPAD];   // ~18.9 MB
__device__ float g_q[TOKENS * 16];
__device__ float g_k[TOKENS * 16];
__device__ float g_w[TOKENS];

// ---- packed f32x2 helpers (FFMA2 path, PTX-only on sm_103a) ----
__device__ __forceinline__ u64 pack2(float lo, float hi) {
    u64 r; asm("mov.b64 %0, {%1, %2};" : "=l"(r) : "f"(lo), "f"(hi)); return r;
}
__device__ __forceinline__ void unpack2(u64 v, float& lo, float& hi) {
    asm("mov.b64 {%0, %1}, %2;" : "=f"(lo), "=f"(hi) : "l"(v));
}
__device__ __forceinline__ u64 fma2(u64 a, u64 b, u64 c) {
    u64 d; asm("fma.rn.f32x2 %0, %1, %2, %3;" : "=l"(d) : "l"(a), "l"(b), "l"(c)); return d;
}

// ============================================================================
// Kernel 1: projection partials. Grid (DSPLIT, 64) = 512 blocks, 256 threads.
// Fusion of the two empirically-best structures:
//   - R9:  W staged ONCE per block (single barrier), x LDG'd directly into
//          registers (16B/lane chunks; adjacent j-iterations complete sectors).
//   - R14: cg = tid&1 splits the 36 padded cols in half per lane -> W
//          fragment per k is 4xLDS.128 + 1xLDS.64 (2-address broadcast,
//          ~5 wavefronts) against 18 FFMA2 (36 fma-cyc): crossbar unbound,
//          ~75% fma density.
// 2 tokens/thread (tg, tg+128), acc = 2 x 9 u64 = 36 regs (vs R9's 68).
// __launch_bounds__(256,3): 3 blocks/SM = 24 warps = 37.5% occupancy.
// ============================================================================
__global__ __launch_bounds__(256, 3)
void proj_kernel(const float* __restrict__ x,
                 const float* __restrict__ Wq,
                 const float* __restrict__ Wk,
                 const float* __restrict__ Ww)
{
    __shared__ float ws[DCHUNK][NCPAD];   // 36.9 KB: full W chunk, staged once

    const int tid   = threadIdx.x;
    const int cg    = tid & 1;        // column half: 0 -> cols 0-15 + {32,33}
    const int tg    = tid >> 1;       //              1 -> cols 16-31 + {34,35}
    const int dbase = blockIdx.x * DCHUNK;
    const int tok0  = blockIdx.y * 256;
    const int t0    = tok0 + tg;
    const int t1    = tok0 + tg + 128;

    // ---- stage W chunk once: 256 rows x 9 float4 ----
    for (int i = tid; i < DCHUNK * 9; i += 256) {
        int row = i / 9, q = i - row * 9;
        float4 v;
        if (q < 4)
            v = *reinterpret_cast<const float4*>(&Wq[(size_t)(dbase + row) * 16 + 4 * q]);
        else if (q < 8)
            v = *reinterpret_cast<const float4*>(&Wk[(size_t)(dbase + row) * 16 + 4 * (q - 4)]);
        else
            v = make_float4(Ww[dbase + row], 0.f, 0.f, 0.f);
        *reinterpret_cast<float4*>(&ws[row][4 * q]) = v;
    }
    __syncthreads();   // the only barrier in the kernel

    u64 acc0[9], acc1[9];
    #pragma unroll
    for (int p = 0; p < 9; p++) { acc0[p] = 0ull; acc1[p] = 0ull; }

    const float* x0 = &x[(size_t)t0 * DMODEL + dbase];
    const float* x1 = &x[(size_t)t1 * DMODEL + dbase];
    const int cbase = cg * 16;

    #pragma unroll 1
    for (int dt = 0; dt < DCHUNK; dt += 16) {
        float4 xa[4], xb[4];
        #pragma unroll
        for (int j = 0; j < 4; j++) {
            xa[j] = *reinterpret_cast<const float4*>(x0 + dt + 4 * j);
            xb[j] = *reinterpret_cast<const float4*>(x1 + dt + 4 * j);
        }
        #pragma unroll
        for (int k = 0; k < 16; k++) {
            const float* wp = &ws[dt + k][cbase];
            const ulonglong2 wA = *reinterpret_cast<const ulonglong2*>(wp);
            const ulonglong2 wB = *reinterpret_cast<const ulonglong2*>(wp + 4);
            const ulonglong2 wC = *reinterpret_cast<const ulonglong2*>(wp + 8);
            const ulonglong2 wD = *reinterpret_cast<const ulonglong2*>(wp + 12);
            const u64 wT = *reinterpret_cast<const u64*>(&ws[dt + k][32 + cg * 2]);

            const float v0 = reinterpret_cast<const float*>(xa)[k];
            const float v1 = reinterpret_cast<const float*>(xb)[k];
            const u64 xv0 = pack2(v0, v0);
            const u64 xv1 = pack2(v1, v1);

            acc0[0] = fma2(xv0, wA.x, acc0[0]);
            acc0[1] = fma2(xv0, wA.y, acc0[1]);
            acc0[2] = fma2(xv0, wB.x, acc0[2]);
            acc0[3] = fma2(xv0, wB.y, acc0[3]);
            acc0[4] = fma2(xv0, wC.x, acc0[4]);
            acc0[5] = fma2(xv0, wC.y, acc0[5]);
            acc0[6] = fma2(xv0, wD.x, acc0[6]);
            acc0[7] = fma2(xv0, wD.y, acc0[7]);
            acc0[8] = fma2(xv0, wT,   acc0[8]);

            acc1[0] = fma2(xv1, wA.x, acc1[0]);
            acc1[1] = fma2(xv1, wA.y, acc1[1]);
            acc1[2] = fma2(xv1, wB.x, acc1[2]);
            acc1[3] = fma2(xv1, wB.y, acc1[3]);
            acc1[4] = fma2(xv1, wC.x, acc1[4]);
            acc1[5] = fma2(xv1, wC.y, acc1[5]);
            acc1[6] = fma2(xv1, wD.x, acc1[6]);
            acc1[7] = fma2(xv1, wD.y, acc1[7]);
            acc1[8] = fma2(xv1, wT,   acc1[8]);
        }
    }

    // ---- write partials: cg0 -> cols 0-15 + {32,33}; cg1 -> 16-31 + {34,35}
    {
        float* p0 = &g_part[((size_t)blockIdx.x * TOKENS + t0) * NCPAD];
        float* p1 = &g_part[((size_t)blockIdx.x * TOKENS + t1) * NCPAD];
        #pragma unroll
        for (int q = 0; q < 4; q++) {
            ulonglong2 v0; v0.x = acc0[2 * q]; v0.y = acc0[2 * q + 1];
            ulonglong2 v1; v1.x = acc1[2 * q]; v1.y = acc1[2 * q + 1];
            *reinterpret_cast<ulonglong2*>(&p0[cbase + 4 * q]) = v0;
            *reinterpret_cast<ulonglong2*>(&p1[cbase + 4 * q]) = v1;
        }
        *reinterpret_cast<u64*>(&p0[32 + cg * 2]) = acc0[8];
        *reinterpret_cast<u64*>(&p1[32 + cg * 2]) = acc1[8];
    }
}

// ============================================================================
// Kernel 2: reduce D-split partials (float4-vectorized, 9 quads/token).
// ============================================================================
__global__ __launch_bounds__(256)
void reduce_kernel()
{
    int i = blockIdx.x * 256 + threadIdx.x;   // 0 .. 16384*9-1
    int tok = i / 9, c4 = i - tok * 9;
    float4 s = make_float4(0.f, 0.f, 0.f, 0.f);
    #pragma unroll
    for (int r = 0; r < DSPLIT; r++) {
        const float4 v = *reinterpret_cast<const float4*>(
            &g_part[((size_t)r * TOKENS + tok) * NCPAD + 4 * c4]);
        s.x += v.x; s.y += v.y; s.z += v.z; s.w += v.w;
    }
    if (c4 < 4)
        *reinterpret_cast<float4*>(&g_q[tok * 16 + 4 * c4]) = s;
    else if (c4 < 8)
        *reinterpret_cast<float4*>(&g_k[tok * 16 + 4 * (c4 - 4)]) = s;
    else
        g_w[tok] = s.x;
}

// ============================================================================
// Kernel 3: out[b,t,s] = relu(Q[b,t] . K[b,s]) * w[b,t]   (R9, unchanged)
// Grid (32 s-tiles, 32 t-tiles, 4) = 4096 blocks, 256 threads.
// Tile 128t x 128s, micro-tile 8t x 8s (s-pairs in f32x2).
// ============================================================================
__device__ __forceinline__ int kt_col(int s) {
    int st = s >> 3;
    return 8 * st + 4 * (st >> 2) + (s & 7);
}

__global__ __launch_bounds__(256)
void dot_kernel(float* __restrict__ out)
{
    __shared__ u64   qs2[128][17];   // [t][d] value-duplicated pairs (17.4 KB)
    __shared__ float kt[16][148];    // [d][s] transposed, swizzled (9.5 KB)
    __shared__ float wts[128];

    const int tid = threadIdx.x;
    const int tt  = tid >> 4;        // 0..15 : t-thread
    const int st  = tid & 15;        // 0..15 : s-thread (8 s each)

    const int b     = blockIdx.z;
    const int tbase = blockIdx.y * 128;
    const int sbase = blockIdx.x * 128;
    const int tokq  = b * SEQ + tbase;
    const int tokk  = b * SEQ + sbase;

    // Stage Q tile duplicated: 128 rows x 16 -> u64 dup pairs
    #pragma unroll
    for (int i = 0; i < 2; i++) {
        int task = tid + 256 * i;
        int row = task >> 2, q = (task & 3) * 4;
        const float4 v = *reinterpret_cast<const float4*>(
            &g_q[(size_t)(tokq + row) * 16 + q]);
        qs2[row][q + 0] = pack2(v.x, v.x);
        qs2[row][q + 1] = pack2(v.y, v.y);
        qs2[row][q + 2] = pack2(v.z, v.z);
        qs2[row][q + 3] = pack2(v.w, v.w);
    }
    // Stage K transposed + swizzled: kt[d][col(s)] = K[s][d]
    #pragma unroll
    for (int i = 0; i < 2; i++) {
        int task = tid + 256 * i;
        int s = task >> 2, q = (task & 3) * 4;
        const float4 v = *reinterpret_cast<const float4*>(
            &g_k[(size_t)(tokk + s) * 16 + q]);
        const int c = kt_col(s);
        kt[q + 0][c] = v.x;
        kt[q + 1][c] = v.y;
        kt[q + 2][c] = v.z;
        kt[q + 3][c] = v.w;
    }
    if (tid < 128) wts[tid] = g_w[tokq + tid];
    __syncthreads();

    const int c0 = 8 * st + 4 * (st >> 2);   // this thread's kt column base

    u64 acc[8][4];
    #pragma unroll
    for (int i = 0; i < 8; i++)
        #pragma unroll
        for (int j = 0; j < 4; j++) acc[i][j] = 0ull;

    #pragma unroll
    for (int d = 0; d < 16; d++) {
        const ulonglong2 ka = *reinterpret_cast<const ulonglong2*>(&kt[d][c0]);
        const ulonglong2 kb = *reinterpret_cast<const ulonglong2*>(&kt[d][c0 + 4]);
        #pragma unroll
        for (int i = 0; i < 8; i++) {
            const u64 q2 = qs2[tt + 16 * i][d];
            acc[i][0] = fma2(q2, ka.x, acc[i][0]);
            acc[i][1] = fma2(q2, ka.y, acc[i][1]);
            acc[i][2] = fma2(q2, kb.x, acc[i][2]);
            acc[i][3] = fma2(q2, kb.y, acc[i][3]);
        }
    }

    // Epilogue: relu, * w[t], 2x STG.128 per row
    #pragma unroll
    for (int i = 0; i < 8; i++) {
        const int t = tbase + tt + 16 * i;
        const float wt = wts[tt + 16 * i];
        float lo, hi;
        float4 oa, ob;
        unpack2(acc[i][0], lo, hi);
        oa.x = fmaxf(lo, 0.f) * wt;  oa.y = fmaxf(hi, 0.f) * wt;
        unpack2(acc[i][1], lo, hi);
        oa.z = fmaxf(lo, 0.f) * wt;  oa.w = fmaxf(hi, 0.f) * wt;
        unpack2(acc[i][2], lo, hi);
        ob.x = fmaxf(lo, 0.f) * wt;  ob.y = fmaxf(hi, 0.f) * wt;
        unpack2(acc[i][3], lo, hi);
        ob.z = fmaxf(lo, 0.f) * wt;  ob.w = fmaxf(hi, 0.f) * wt;
        float* o = &out[((size_t)(b * SEQ + t)) * SEQ + sbase + st * 8];
        *reinterpret_cast<float4*>(o)     = oa;
        *reinterpret_cast<float4*>(o + 4) = ob;
    }
}

// ============================================================================
extern "C" void kernel_launch(void* const* d_in, const int* in_sizes, int n_in,
                              void* d_out, int out_size)
{
    const float* x  = (const float*)d_in[0];
    const float* Wq = (const float*)d_in[1];
    const float* Wk = (const float*)d_in[2];
    const float* Ww = (const float*)d_in[3];
    float* out = (float*)d_out;

    proj_kernel<<<dim3(DSPLIT, TOKENS / 256), 256>>>(x, Wq, Wk, Ww);
    reduce_kernel<<<(TOKENS * 9) / 256, 256>>>();
    dot_kernel<<<dim3(SEQ / 128, SEQ / 128, BATCH), 256>>>(out);
}

// round 17
// speedup vs baseline: 1.5230x; 1.0402x over previous
#include <cuda_runtime.h>
#include <cstdint>

// Problem constants
#define BATCH   4
#define SEQ     4096
#define DMODEL  2048
#define TOKENS  (BATCH * SEQ)     // 16384
#define NCPAD   36                // 16 q + 16 k + w + pad (float4-aligned pitch)
#define DSPLIT  8
#define DCHUNK  (DMODEL / DSPLIT) // 256

typedef unsigned long long u64;

// Scratch (static device globals: no dynamic allocation allowed)
__device__ float g_part[(size_t)DSPLIT * TOKENS * NCPAD];   // ~18.9 MB
__device__ float g_q[TOKENS * 16];
__device__ float g_k[TOKENS * 16];
__device__ float g_w[TOKENS];

// ---- packed f32x2 helpers (FFMA2 path, PTX-only on sm_103a) ----
__device__ __forceinline__ u64 pack2(float lo, float hi) {
    u64 r; asm("mov.b64 %0, {%1, %2};" : "=l"(r) : "f"(lo), "f"(hi)); return r;
}
__device__ __forceinline__ void unpack2(u64 v, float& lo, float& hi) {
    asm("mov.b64 {%0, %1}, %2;" : "=f"(lo), "=f"(hi) : "l"(v));
}
__device__ __forceinline__ u64 fma2(u64 a, u64 b, u64 c) {
    u64 d; asm("fma.rn.f32x2 %0, %1, %2, %3;" : "=l"(d) : "l"(a), "l"(b), "l"(c)); return d;
}

// ============================================================================
// Kernel 1: projection partials. Grid (DSPLIT, 64) = 512 blocks, 256 threads.
// R15 structure (W staged once, single barrier; cg = tid&1 col-split for
// ~75% fma density; 2 tokens/thread) + REGISTER DOUBLE-BUFFERING of x tiles:
// tile t+1's 8 float4 are LDG'd while tile t computes, 2-tile unrolled ring,
// so the per-tile DRAM latency (~600cyc vs 576cyc compute) that capped
// R9/R12/R15 at ~33% issue is hidden in-warp (MLP=8).
// __launch_bounds__(256,2): <=128 regs, 16 warps/SM.
// ============================================================================
__global__ __launch_bounds__(256, 2)
void proj_kernel(const float* __restrict__ x,
                 const float* __restrict__ Wq,
                 const float* __restrict__ Wk,
                 const float* __restrict__ Ww)
{
    __shared__ float ws[DCHUNK][NCPAD];   // 36.9 KB: full W chunk, staged once

    const int tid   = threadIdx.x;
    const int cg    = tid & 1;        // column half: 0 -> cols 0-15 + {32,33}
    const int tg    = tid >> 1;       //              1 -> cols 16-31 + {34,35}
    const int dbase = blockIdx.x * DCHUNK;
    const int tok0  = blockIdx.y * 256;
    const int t0    = tok0 + tg;
    const int t1    = tok0 + tg + 128;

    // ---- stage W chunk once: 256 rows x 9 float4 ----
    for (int i = tid; i < DCHUNK * 9; i += 256) {
        int row = i / 9, q = i - row * 9;
        float4 v;
        if (q < 4)
            v = *reinterpret_cast<const float4*>(&Wq[(size_t)(dbase + row) * 16 + 4 * q]);
        else if (q < 8)
            v = *reinterpret_cast<const float4*>(&Wk[(size_t)(dbase + row) * 16 + 4 * (q - 4)]);
        else
            v = make_float4(Ww[dbase + row], 0.f, 0.f, 0.f);
        *reinterpret_cast<float4*>(&ws[row][4 * q]) = v;
    }
    __syncthreads();   // the only barrier in the kernel

    u64 acc0[9], acc1[9];
    #pragma unroll
    for (int p = 0; p < 9; p++) { acc0[p] = 0ull; acc1[p] = 0ull; }

    const float* x0 = &x[(size_t)t0 * DMODEL + dbase];
    const float* x1 = &x[(size_t)t1 * DMODEL + dbase];
    const int cbase = cg * 16;

    // ---- 16-d tile compute from registers ----
    auto compute16 = [&](const float4 (&xa)[4], const float4 (&xb)[4], int dt) {
        #pragma unroll
        for (int k = 0; k < 16; k++) {
            const float* wp = &ws[dt + k][cbase];
            const ulonglong2 wA = *reinterpret_cast<const ulonglong2*>(wp);
            const ulonglong2 wB = *reinterpret_cast<const ulonglong2*>(wp + 4);
            const ulonglong2 wC = *reinterpret_cast<const ulonglong2*>(wp + 8);
            const ulonglong2 wD = *reinterpret_cast<const ulonglong2*>(wp + 12);
            const u64 wT = *reinterpret_cast<const u64*>(&ws[dt + k][32 + cg * 2]);

            const float v0 = reinterpret_cast<const float*>(xa)[k];
            const float v1 = reinterpret_cast<const float*>(xb)[k];
            const u64 xv0 = pack2(v0, v0);
            const u64 xv1 = pack2(v1, v1);

            acc0[0] = fma2(xv0, wA.x, acc0[0]);
            acc0[1] = fma2(xv0, wA.y, acc0[1]);
            acc0[2] = fma2(xv0, wB.x, acc0[2]);
            acc0[3] = fma2(xv0, wB.y, acc0[3]);
            acc0[4] = fma2(xv0, wC.x, acc0[4]);
            acc0[5] = fma2(xv0, wC.y, acc0[5]);
            acc0[6] = fma2(xv0, wD.x, acc0[6]);
            acc0[7] = fma2(xv0, wD.y, acc0[7]);
            acc0[8] = fma2(xv0, wT,   acc0[8]);

            acc1[0] = fma2(xv1, wA.x, acc1[0]);
            acc1[1] = fma2(xv1, wA.y, acc1[1]);
            acc1[2] = fma2(xv1, wB.x, acc1[2]);
            acc1[3] = fma2(xv1, wB.y, acc1[3]);
            acc1[4] = fma2(xv1, wC.x, acc1[4]);
            acc1[5] = fma2(xv1, wC.y, acc1[5]);
            acc1[6] = fma2(xv1, wD.x, acc1[6]);
            acc1[7] = fma2(xv1, wD.y, acc1[7]);
            acc1[8] = fma2(xv1, wT,   acc1[8]);
        }
    };

    float4 A0[4], B0[4], A1[4], B1[4];
    #pragma unroll
    for (int j = 0; j < 4; j++) {
        A0[j] = *reinterpret_cast<const float4*>(x0 + 4 * j);
        B0[j] = *reinterpret_cast<const float4*>(x1 + 4 * j);
    }

    #pragma unroll 1
    for (int dt = 0; dt < DCHUNK; dt += 32) {
        // prefetch tile dt+16 while computing tile dt
        #pragma unroll
        for (int j = 0; j < 4; j++) {
            A1[j] = *reinterpret_cast<const float4*>(x0 + dt + 16 + 4 * j);
            B1[j] = *reinterpret_cast<const float4*>(x1 + dt + 16 + 4 * j);
        }
        compute16(A0, B0, dt);
        // prefetch tile dt+32 while computing tile dt+16
        if (dt + 32 < DCHUNK) {
            #pragma unroll
            for (int j = 0; j < 4; j++) {
                A0[j] = *reinterpret_cast<const float4*>(x0 + dt + 32 + 4 * j);
                B0[j] = *reinterpret_cast<const float4*>(x1 + dt + 32 + 4 * j);
            }
        }
        compute16(A1, B1, dt + 16);
    }

    // ---- write partials: cg0 -> cols 0-15 + {32,33}; cg1 -> 16-31 + {34,35}
    {
        float* p0 = &g_part[((size_t)blockIdx.x * TOKENS + t0) * NCPAD];
        float* p1 = &g_part[((size_t)blockIdx.x * TOKENS + t1) * NCPAD];
        #pragma unroll
        for (int q = 0; q < 4; q++) {
            ulonglong2 v0; v0.x = acc0[2 * q]; v0.y = acc0[2 * q + 1];
            ulonglong2 v1; v1.x = acc1[2 * q]; v1.y = acc1[2 * q + 1];
            *reinterpret_cast<ulonglong2*>(&p0[cg * 16 + 4 * q]) = v0;
            *reinterpret_cast<ulonglong2*>(&p1[cg * 16 + 4 * q]) = v1;
        }
        *reinterpret_cast<u64*>(&p0[32 + cg * 2]) = acc0[8];
        *reinterpret_cast<u64*>(&p1[32 + cg * 2]) = acc1[8];
    }
}

// ============================================================================
// Kernel 2: reduce D-split partials (float4-vectorized, 9 quads/token).
// ============================================================================
__global__ __launch_bounds__(256)
void reduce_kernel()
{
    int i = blockIdx.x * 256 + threadIdx.x;   // 0 .. 16384*9-1
    int tok = i / 9, c4 = i - tok * 9;
    float4 s = make_float4(0.f, 0.f, 0.f, 0.f);
    #pragma unroll
    for (int r = 0; r < DSPLIT; r++) {
        const float4 v = *reinterpret_cast<const float4*>(
            &g_part[((size_t)r * TOKENS + tok) * NCPAD + 4 * c4]);
        s.x += v.x; s.y += v.y; s.z += v.z; s.w += v.w;
    }
    if (c4 < 4)
        *reinterpret_cast<float4*>(&g_q[tok * 16 + 4 * c4]) = s;
    else if (c4 < 8)
        *reinterpret_cast<float4*>(&g_k[tok * 16 + 4 * (c4 - 4)]) = s;
    else
        g_w[tok] = s.x;
}

// ============================================================================
// Kernel 3: out[b,t,s] = relu(Q[b,t] . K[b,s]) * w[b,t]   (R9, unchanged)
// Grid (32 s-tiles, 32 t-tiles, 4) = 4096 blocks, 256 threads.
// Tile 128t x 128s, micro-tile 8t x 8s (s-pairs in f32x2).
// ============================================================================
__device__ __forceinline__ int kt_col(int s) {
    int st = s >> 3;
    return 8 * st + 4 * (st >> 2) + (s & 7);
}

__global__ __launch_bounds__(256)
void dot_kernel(float* __restrict__ out)
{
    __shared__ u64   qs2[128][17];   // [t][d] value-duplicated pairs (17.4 KB)
    __shared__ float kt[16][148];    // [d][s] transposed, swizzled (9.5 KB)
    __shared__ float wts[128];

    const int tid = threadIdx.x;
    const int tt  = tid >> 4;        // 0..15 : t-thread
    const int st  = tid & 15;        // 0..15 : s-thread (8 s each)

    const int b     = blockIdx.z;
    const int tbase = blockIdx.y * 128;
    const int sbase = blockIdx.x * 128;
    const int tokq  = b * SEQ + tbase;
    const int tokk  = b * SEQ + sbase;

    // Stage Q tile duplicated: 128 rows x 16 -> u64 dup pairs
    #pragma unroll
    for (int i = 0; i < 2; i++) {
        int task = tid + 256 * i;
        int row = task >> 2, q = (task & 3) * 4;
        const float4 v = *reinterpret_cast<const float4*>(
            &g_q[(size_t)(tokq + row) * 16 + q]);
        qs2[row][q + 0] = pack2(v.x, v.x);
        qs2[row][q + 1] = pack2(v.y, v.y);
        qs2[row][q + 2] = pack2(v.z, v.z);
        qs2[row][q + 3] = pack2(v.w, v.w);
    }
    // Stage K transposed + swizzled: kt[d][col(s)] = K[s][d]
    #pragma unroll
    for (int i = 0; i < 2; i++) {
        int task = tid + 256 * i;
        int s = task >> 2, q = (task & 3) * 4;
        const float4 v = *reinterpret_cast<const float4*>(
            &g_k[(size_t)(tokk + s) * 16 + q]);
        const int c = kt_col(s);
        kt[q + 0][c] = v.x;
        kt[q + 1][c] = v.y;
        kt[q + 2][c] = v.z;
        kt[q + 3][c] = v.w;
    }
    if (tid < 128) wts[tid] = g_w[tokq + tid];
    __syncthreads();

    const int c0 = 8 * st + 4 * (st >> 2);   // this thread's kt column base

    u64 acc[8][4];
    #pragma unroll
    for (int i = 0; i < 8; i++)
        #pragma unroll
        for (int j = 0; j < 4; j++) acc[i][j] = 0ull;

    #pragma unroll
    for (int d = 0; d < 16; d++) {
        const ulonglong2 ka = *reinterpret_cast<const ulonglong2*>(&kt[d][c0]);
        const ulonglong2 kb = *reinterpret_cast<const ulonglong2*>(&kt[d][c0 + 4]);
        #pragma unroll
        for (int i = 0; i < 8; i++) {
            const u64 q2 = qs2[tt + 16 * i][d];
            acc[i][0] = fma2(q2, ka.x, acc[i][0]);
            acc[i][1] = fma2(q2, ka.y, acc[i][1]);
            acc[i][2] = fma2(q2, kb.x, acc[i][2]);
            acc[i][3] = fma2(q2, kb.y, acc[i][3]);
        }
    }

    // Epilogue: relu, * w[t], 2x STG.128 per row
    #pragma unroll
    for (int i = 0; i < 8; i++) {
        const int t = tbase + tt + 16 * i;
        const float wt = wts[tt + 16 * i];
        float lo, hi;
        float4 oa, ob;
        unpack2(acc[i][0], lo, hi);
        oa.x = fmaxf(lo, 0.f) * wt;  oa.y = fmaxf(hi, 0.f) * wt;
        unpack2(acc[i][1], lo, hi);
        oa.z = fmaxf(lo, 0.f) * wt;  oa.w = fmaxf(hi, 0.f) * wt;
        unpack2(acc[i][2], lo, hi);
        ob.x = fmaxf(lo, 0.f) * wt;  ob.y = fmaxf(hi, 0.f) * wt;
        unpack2(acc[i][3], lo, hi);
        ob.z = fmaxf(lo, 0.f) * wt;  ob.w = fmaxf(hi, 0.f) * wt;
        float* o = &out[((size_t)(b * SEQ + t)) * SEQ + sbase + st * 8];
        *reinterpret_cast<float4*>(o)     = oa;
        *reinterpret_cast<float4*>(o + 4) = ob;
    }
}

// ============================================================================
extern "C" void kernel_launch(void* const* d_in, const int* in_sizes, int n_in,
                              void* d_out, int out_size)
{
    const float* x  = (const float*)d_in[0];
    const float* Wq = (const float*)d_in[1];
    const float* Wk = (const float*)d_in[2];
    const float* Ww = (const float*)d_in[3];
    float* out = (float*)d_out;

    proj_kernel<<<dim3(DSPLIT, TOKENS / 256), 256>>>(x, Wq, Wk, Ww);
    reduce_kernel<<<(TOKENS * 9) / 256, 256>>>();
    dot_kernel<<<dim3(SEQ / 128, SEQ / 128, BATCH), 256>>>(out);
}